// round 2
// baseline (speedup 1.0000x reference)
#include <cuda_runtime.h>
#include <cuda_fp16.h>
#include <cstdint>

#define NVARS 256
#define BM 64
#define SROW 264   // halves per smem row (528 B): 132 words ≡ 4 banks mod 32 -> conflict-free ldmatrix

// B operand: g_W[n][k] = V[n][k] for k>n, else 0 (V = M^{-1}; identity added in fp32 epilogue)
__device__ __half g_W[NVARS * NVARS];

__device__ __forceinline__ uint32_t smem_to_u32(const void* smem_ptr) {
    uint32_t addr;
    asm("{ .reg .u64 tmp; cvta.to.shared.u64 tmp, %1; cvt.u32.u64 %0, tmp; }"
        : "=r"(addr) : "l"(smem_ptr));
    return addr;
}

__device__ __forceinline__ void ldmx4(uint32_t* d, uint32_t addr) {
    asm volatile("ldmatrix.sync.aligned.m8n8.x4.shared.b16 {%0,%1,%2,%3}, [%4];"
                 : "=r"(d[0]), "=r"(d[1]), "=r"(d[2]), "=r"(d[3])
                 : "r"(addr));
}

__device__ __forceinline__ void mma16816(float* c, const uint32_t* a,
                                         uint32_t b0, uint32_t b1) {
    asm volatile(
        "mma.sync.aligned.m16n8k16.row.col.f32.f16.f16.f32 "
        "{%0,%1,%2,%3}, {%4,%5,%6,%7}, {%8,%9}, {%0,%1,%2,%3};"
        : "+f"(c[0]), "+f"(c[1]), "+f"(c[2]), "+f"(c[3])
        : "r"(a[0]), "r"(a[1]), "r"(a[2]), "r"(a[3]), "r"(b0), "r"(b1));
}

// ---------------------------------------------------------------------------
// Kernel 1: invert unit upper-triangular M = I - tril(A,-1)^T.
// V[r][c] = sum_{j=r}^{c-1} V[r][j] * A[c][j];  one warp per row, 2 cols/round.
// ---------------------------------------------------------------------------
__global__ __launch_bounds__(128) void invert_kernel(const float* __restrict__ A) {
    __shared__ float Vsm_all[4][NVARS];
    const int warp = threadIdx.x >> 5;
    const int lane = threadIdx.x & 31;
    const int r = blockIdx.x * 4 + warp;
    float* Vsm = Vsm_all[warp];

    if (lane == 0) Vsm[r] = 1.0f;
    __syncwarp();

    int c = r + 1;
    for (; c + 1 < NVARS; c += 2) {
        const float* Ac0 = A + c * NVARS;
        const float* Ac1 = Ac0 + NVARS;
        float s0 = 0.0f, s1 = 0.0f;
        for (int j = r + lane; j < c; j += 32) {
            const float v = Vsm[j];
            s0 = fmaf(v, Ac0[j], s0);
            s1 = fmaf(v, Ac1[j], s1);
        }
#pragma unroll
        for (int o = 16; o; o >>= 1) {
            s0 += __shfl_xor_sync(0xffffffffu, s0, o);
            s1 += __shfl_xor_sync(0xffffffffu, s1, o);
        }
        if (lane == 0) {
            Vsm[c] = s0;
            Vsm[c + 1] = fmaf(s0, Ac1[c], s1);  // add missing j=c term
        }
        __syncwarp();
    }
    if (c < NVARS) {
        const float* Ac0 = A + c * NVARS;
        float s0 = 0.0f;
        for (int j = r + lane; j < c; j += 32)
            s0 = fmaf(Vsm[j], Ac0[j], s0);
#pragma unroll
        for (int o = 16; o; o >>= 1)
            s0 += __shfl_xor_sync(0xffffffffu, s0, o);
        if (lane == 0) Vsm[c] = s0;
        __syncwarp();
    }

    for (int k = lane; k < NVARS; k += 32)
        g_W[r * NVARS + k] = __float2half((k > r) ? Vsm[k] : 0.0f);
}

// ---------------------------------------------------------------------------
// Kernel 2: out[m][n] = Z[m][n] + sum_k Z[m][k] * g_W[n][k]
// CTA: 64(M) x 256(N) x 256(K); 8 warps (2x4), warp tile 32x64.
// ---------------------------------------------------------------------------
static constexpr int SMEM_Z_HALVES = BM * SROW;         // 16896
static constexpr int SMEM_W_HALVES = NVARS * SROW;      // 67584
static constexpr int SMEM_BYTES = (SMEM_Z_HALVES + SMEM_W_HALVES) * 2;  // 168960

__global__ __launch_bounds__(256, 1) void gemm_kernel(const float* __restrict__ Z,
                                                      float* __restrict__ out,
                                                      int batch) {
    extern __shared__ __align__(16) __half smem[];
    __half* Zs = smem;
    __half* Ws = smem + SMEM_Z_HALVES;

    const int tid = threadIdx.x;
    const int lane = tid & 31;
    const int wid = tid >> 5;
    const int wm = wid & 1;   // 0..1  (M half: 32 rows each)
    const int wn = wid >> 1;  // 0..3  (N quarter: 64 cols each)
    const int m0 = blockIdx.x * BM;

    // --- stage Z (fp32 -> fp16) : 64 rows x 256 cols ---
    for (int idx = tid; idx < BM * 32; idx += 256) {
        const int row = idx >> 5;
        const int seg = idx & 31;  // 8 halves per segment
        uint4 u = make_uint4(0, 0, 0, 0);
        const int gr = m0 + row;
        if (gr < batch) {
            const float4* p = reinterpret_cast<const float4*>(Z + (size_t)gr * NVARS + seg * 8);
            const float4 f0 = p[0], f1 = p[1];
            __half2 h0 = __floats2half2_rn(f0.x, f0.y);
            __half2 h1 = __floats2half2_rn(f0.z, f0.w);
            __half2 h2 = __floats2half2_rn(f1.x, f1.y);
            __half2 h3 = __floats2half2_rn(f1.z, f1.w);
            u.x = *reinterpret_cast<uint32_t*>(&h0);
            u.y = *reinterpret_cast<uint32_t*>(&h1);
            u.z = *reinterpret_cast<uint32_t*>(&h2);
            u.w = *reinterpret_cast<uint32_t*>(&h3);
        }
        *reinterpret_cast<uint4*>(Zs + row * SROW + seg * 8) = u;
    }
    // --- stage W (fp16) : 256 rows x 256 cols ---
    for (int idx = tid; idx < NVARS * 32; idx += 256) {
        const int row = idx >> 5;
        const int seg = idx & 31;
        *reinterpret_cast<uint4*>(Ws + row * SROW + seg * 8) =
            *reinterpret_cast<const uint4*>(g_W + row * NVARS + seg * 8);
    }
    __syncthreads();

    // --- fragment addresses ---
    const uint32_t zbase = smem_to_u32(Zs);
    const uint32_t wbase = smem_to_u32(Ws);
    // A (Z): per 16x16 tile, lane -> row = (lane&15), col-half = (lane&16)?8:0
    uint32_t aaddr[2];
#pragma unroll
    for (int mi = 0; mi < 2; ++mi) {
        const int row = wm * 32 + mi * 16 + (lane & 15);
        const int cb = ((lane >> 4) & 1) * 16;  // bytes
        aaddr[mi] = zbase + (uint32_t)row * (SROW * 2) + cb;
    }
    // B (W): per n16xk16 block, lanes 0-7:n0-7/k0-7, 8-15:n0-7/k8-15, 16-23:n8-15/k0-7, 24-31:n8-15/k8-15
    uint32_t baddr[4];
#pragma unroll
    for (int bj = 0; bj < 4; ++bj) {
        const int row = wn * 64 + bj * 16 + (lane & 7) + (((lane >> 4) & 1) * 8);
        const int cb = (lane & 8) ? 16 : 0;
        baddr[bj] = wbase + (uint32_t)row * (SROW * 2) + cb;
    }

    // --- mainloop: K = 256 = 16 steps of k16 ---
    float acc[2][8][4];
#pragma unroll
    for (int mi = 0; mi < 2; ++mi)
#pragma unroll
        for (int nj = 0; nj < 8; ++nj)
#pragma unroll
            for (int e = 0; e < 4; ++e) acc[mi][nj][e] = 0.0f;

#pragma unroll
    for (int k = 0; k < 16; ++k) {
        uint32_t a[2][4], b[4][4];
#pragma unroll
        for (int mi = 0; mi < 2; ++mi) ldmx4(a[mi], aaddr[mi] + k * 32);
#pragma unroll
        for (int bj = 0; bj < 4; ++bj) ldmx4(b[bj], baddr[bj] + k * 32);
#pragma unroll
        for (int mi = 0; mi < 2; ++mi) {
#pragma unroll
            for (int nj = 0; nj < 8; ++nj) {
                const int bj = nj >> 1;
                const int hi = (nj & 1) * 2;
                mma16816(acc[mi][nj], a[mi], b[bj][hi + 0], b[bj][hi + 1]);
            }
        }
    }

    // --- epilogue: out = Z(fp32) + acc ---
    const int rrow = lane >> 2;
    const int rcol = (lane & 3) * 2;
#pragma unroll
    for (int mi = 0; mi < 2; ++mi) {
#pragma unroll
        for (int nj = 0; nj < 8; ++nj) {
            const int r0 = m0 + wm * 32 + mi * 16 + rrow;
            const int c = wn * 64 + nj * 8 + rcol;
            if (r0 < batch) {
                const float2 z0 = *reinterpret_cast<const float2*>(Z + (size_t)r0 * NVARS + c);
                float2 o0;
                o0.x = z0.x + acc[mi][nj][0];
                o0.y = z0.y + acc[mi][nj][1];
                *reinterpret_cast<float2*>(out + (size_t)r0 * NVARS + c) = o0;
            }
            const int r1 = r0 + 8;
            if (r1 < batch) {
                const float2 z1 = *reinterpret_cast<const float2*>(Z + (size_t)r1 * NVARS + c);
                float2 o1;
                o1.x = z1.x + acc[mi][nj][2];
                o1.y = z1.y + acc[mi][nj][3];
                *reinterpret_cast<float2*>(out + (size_t)r1 * NVARS + c) = o1;
            }
        }
    }
}

// ---------------------------------------------------------------------------
extern "C" void kernel_launch(void* const* d_in, const int* in_sizes, int n_in,
                              void* d_out, int out_size) {
    const float* Z = (const float*)d_in[0];
    const float* A = (const float*)d_in[1];
    float* out = (float*)d_out;
    const int batch = in_sizes[0] / NVARS;

    cudaFuncSetAttribute(gemm_kernel, cudaFuncAttributeMaxDynamicSharedMemorySize,
                         SMEM_BYTES);

    invert_kernel<<<NVARS / 4, 128>>>(A);
    const int grid = (batch + BM - 1) / BM;
    gemm_kernel<<<grid, 256, SMEM_BYTES>>>(Z, out, batch);
}

// round 3
// speedup vs baseline: 1.7557x; 1.7557x over previous
#include <cuda_runtime.h>
#include <cuda_fp16.h>
#include <cstdint>

#define NVARS 256
#define BM 32
#define SROW 264  // halves per smem row (528B): conflict-free ldmatrix phases

// W[n][k] = V[n][k] for k>n else 0  (V = M^{-1}; identity added in fp32 epilogue)
__device__ __half g_W[NVARS * NVARS];
// At[j][i] = A[i][j], fp16 (history reads coalesced)
__device__ __half g_At[NVARS * NVARS];
// Binv[d][u][t] = inv(I - Ublk_d), fp32, Ublk_d[u][t] = A[32d+t][32d+u] (u<t)
__device__ float g_Binv[8 * 32 * 32];

__device__ __forceinline__ uint32_t smem_to_u32(const void* smem_ptr) {
    uint32_t addr;
    asm("{ .reg .u64 tmp; cvta.to.shared.u64 tmp, %1; cvt.u32.u64 %0, tmp; }"
        : "=r"(addr) : "l"(smem_ptr));
    return addr;
}

__device__ __forceinline__ void ldmx4(uint32_t* d, uint32_t addr) {
    asm volatile("ldmatrix.sync.aligned.m8n8.x4.shared.b16 {%0,%1,%2,%3}, [%4];"
                 : "=r"(d[0]), "=r"(d[1]), "=r"(d[2]), "=r"(d[3])
                 : "r"(addr));
}

__device__ __forceinline__ void mma16816(float* c, const uint32_t* a,
                                         uint32_t b0, uint32_t b1) {
    asm volatile(
        "mma.sync.aligned.m16n8k16.row.col.f32.f16.f16.f32 "
        "{%0,%1,%2,%3}, {%4,%5,%6,%7}, {%8,%9}, {%0,%1,%2,%3};"
        : "+f"(c[0]), "+f"(c[1]), "+f"(c[2]), "+f"(c[3])
        : "r"(a[0]), "r"(a[1]), "r"(a[2]), "r"(a[3]), "r"(b0), "r"(b1));
}

// ---------------------------------------------------------------------------
// Kernel A: transpose A (fp32) -> g_At (fp16). grid (8,8), block (32,8).
// ---------------------------------------------------------------------------
__global__ void transpose_kernel(const float* __restrict__ A) {
    __shared__ float tile[32][33];
    const int tx = threadIdx.x, ty = threadIdx.y;
    const int i0 = blockIdx.y * 32, j0 = blockIdx.x * 32;
#pragma unroll
    for (int k = 0; k < 4; ++k)
        tile[ty + 8 * k][tx] = A[(size_t)(i0 + ty + 8 * k) * NVARS + j0 + tx];
    __syncthreads();
#pragma unroll
    for (int k = 0; k < 4; ++k)
        g_At[(size_t)(j0 + ty + 8 * k) * NVARS + i0 + tx] =
            __float2half(tile[tx][ty + 8 * k]);
}

// ---------------------------------------------------------------------------
// Kernel B: invert the 8 diagonal 32x32 blocks. 1 CTA x 256 threads.
// Binv row recurrence (lane u owns row u of block d = warp id):
//   B[u][t] = sum_{x=u}^{t-1} B[u][x] * A[(c0+t)][(c0+x)],  B[u][u] = 1.
// ---------------------------------------------------------------------------
__global__ __launch_bounds__(256) void blockinv_kernel(const float* __restrict__ A) {
    __shared__ float Bs[8][32][33];
    const int d = threadIdx.x >> 5;
    const int u = threadIdx.x & 31;
    const int c0 = d * 32;
    float (*B)[33] = Bs[d];

#pragma unroll
    for (int t = 0; t < 32; ++t) B[u][t] = 0.0f;
    B[u][u] = 1.0f;

    for (int t = 1; t < 32; ++t) {
        if (t > u) {
            float s = 0.0f;
            const float* Arow = A + (size_t)(c0 + t) * NVARS + c0;
            for (int x = u; x < t; ++x)
                s = fmaf(B[u][x], Arow[x], s);
            B[u][t] = s;
        }
    }
    // write out coalesced (row u of block d)
    for (int i = u; i < 1024; i += 32) {
        const int uu = i >> 5, tt = i & 31;
        g_Binv[d * 1024 + i] = B[uu][tt];
    }
}

// ---------------------------------------------------------------------------
// Kernel C: main triangular inverse. 32 CTAs x 256 threads; warp per row r.
// V[r][c] = delta_rc + sum_{j=r}^{c-1} V[r][j] * A[c][j]
// Per 32-col block: history sums in parallel (lane t), then v = s . Binv_d.
// ---------------------------------------------------------------------------
__global__ __launch_bounds__(256) void invmain_kernel() {
    __shared__ float Binv_s[8 * 32 * 32];  // 32KB
    __shared__ float Vsm_all[8][NVARS];    // 8KB
    const int tid = threadIdx.x;
    const int warp = tid >> 5;
    const int lane = tid & 31;
    const int r = blockIdx.x * 8 + warp;
    float* Vsm = Vsm_all[warp];

    for (int idx = tid; idx < 8192; idx += 256) Binv_s[idx] = g_Binv[idx];
    __syncthreads();

    const int d0 = r >> 5;
    // zero the below-diagonal blocks of W row r
    for (int d = 0; d < d0; ++d)
        g_W[r * NVARS + d * 32 + lane] = __float2half(0.0f);

    const int j0 = d0 * 32;
    for (int d = d0; d < 8; ++d) {
        const int c0 = d * 32;
        float S;
        if (d == d0) {
            S = (lane == (r & 31)) ? 1.0f : 0.0f;
        } else {
            float s0 = 0.f, s1 = 0.f, s2 = 0.f, s3 = 0.f;
            const __half* At = g_At + c0 + lane;
#pragma unroll 2
            for (int j = j0; j < c0; j += 4) {
                s0 = fmaf(Vsm[j + 0], __half2float(At[(j + 0) * NVARS]), s0);
                s1 = fmaf(Vsm[j + 1], __half2float(At[(j + 1) * NVARS]), s1);
                s2 = fmaf(Vsm[j + 2], __half2float(At[(j + 2) * NVARS]), s2);
                s3 = fmaf(Vsm[j + 3], __half2float(At[(j + 3) * NVARS]), s3);
            }
            S = (s0 + s1) + (s2 + s3);
        }
        // v[t] = sum_u s[u] * Binv_d[u][t]
        float v = 0.0f;
        const float* Bi = Binv_s + d * 1024 + lane;
#pragma unroll
        for (int u = 0; u < 32; ++u) {
            const float su = __shfl_sync(0xffffffffu, S, u);
            v = fmaf(su, Bi[u * 32], v);
        }
        Vsm[c0 + lane] = v;
        __syncwarp();
        g_W[r * NVARS + c0 + lane] = __float2half((c0 + lane > r) ? v : 0.0f);
    }
}

// ---------------------------------------------------------------------------
// Kernel D: persistent GEMM. out[m][n] = Z[m][n] + sum_k Z[m][k] * W[n][k]
// W resident in smem (loaded once per CTA); Z tiles (BM=32) register-
// prefetched + double-buffered in smem. 8 warps: 2(M,16) x 4(N,64).
// ---------------------------------------------------------------------------
static constexpr int SMEM_W_HALVES = NVARS * SROW;              // 67584
static constexpr int SMEM_Z_HALVES = BM * SROW;                 // 8448 per buf
static constexpr int SMEM_BYTES = (SMEM_W_HALVES + 2 * SMEM_Z_HALVES) * 2;  // 168960

__global__ __launch_bounds__(256, 1) void gemm_kernel(const float* __restrict__ Z,
                                                      float* __restrict__ out,
                                                      int batch, int ntiles) {
    extern __shared__ __align__(16) __half smem[];
    __half* Ws = smem;
    __half* Zbuf0 = smem + SMEM_W_HALVES;
    __half* Zbuf1 = Zbuf0 + SMEM_Z_HALVES;

    const int tid = threadIdx.x;
    const int lane = tid & 31;
    const int wid = tid >> 5;
    const int wm = wid & 1;   // M half (16 rows)
    const int wn = wid >> 1;  // N quarter (64 cols)

    // --- load W into smem once ---
    for (int idx = tid; idx < NVARS * 32; idx += 256) {
        const int row = idx >> 5;
        const int seg = idx & 31;
        *reinterpret_cast<uint4*>(Ws + row * SROW + seg * 8) =
            *reinterpret_cast<const uint4*>(g_W + row * NVARS + seg * 8);
    }

    // --- B fragment addresses (W fixed) ---
    const uint32_t wbase = smem_to_u32(Ws);
    uint32_t baddr[4];
#pragma unroll
    for (int bj = 0; bj < 4; ++bj) {
        const int row = wn * 64 + bj * 16 + (lane & 7) + (((lane >> 4) & 1) * 8);
        const int cb = (lane & 8) ? 16 : 0;
        baddr[bj] = wbase + (uint32_t)row * (SROW * 2) + cb;
    }
    const int arow = wm * 16 + (lane & 15);
    const uint32_t acb = ((lane >> 4) & 1) * 16;

    // --- prefetch first tile into registers ---
    const int prow = tid >> 3;        // 32 rows, 8 threads/row
    const int pseg = tid & 7;         // not used; see idx mapping below
    (void)prow; (void)pseg;
    float4 pf[8];
    int tile = blockIdx.x;
    {
        const int t0 = tile;
#pragma unroll
        for (int i = 0; i < 4; ++i) {
            const int idx = tid + i * 256;
            const int row = idx >> 5, seg = idx & 31;
            const int gr = t0 * BM + row;
            if (t0 < ntiles && gr < batch) {
                const float4* p =
                    reinterpret_cast<const float4*>(Z + (size_t)gr * NVARS + seg * 8);
                pf[2 * i] = p[0];
                pf[2 * i + 1] = p[1];
            } else {
                pf[2 * i] = make_float4(0, 0, 0, 0);
                pf[2 * i + 1] = make_float4(0, 0, 0, 0);
            }
        }
    }

    int parity = 0;
    const int rrow = lane >> 2;
    const int rcol = (lane & 3) * 2;

    for (; tile < ntiles; tile += gridDim.x) {
        __half* Zs = parity ? Zbuf1 : Zbuf0;

        // convert prefetched regs -> fp16 smem
#pragma unroll
        for (int i = 0; i < 4; ++i) {
            const int idx = tid + i * 256;
            const int row = idx >> 5, seg = idx & 31;
            const float4 f0 = pf[2 * i], f1 = pf[2 * i + 1];
            __half2 h0 = __floats2half2_rn(f0.x, f0.y);
            __half2 h1 = __floats2half2_rn(f0.z, f0.w);
            __half2 h2 = __floats2half2_rn(f1.x, f1.y);
            __half2 h3 = __floats2half2_rn(f1.z, f1.w);
            uint4 u;
            u.x = *reinterpret_cast<uint32_t*>(&h0);
            u.y = *reinterpret_cast<uint32_t*>(&h1);
            u.z = *reinterpret_cast<uint32_t*>(&h2);
            u.w = *reinterpret_cast<uint32_t*>(&h3);
            *reinterpret_cast<uint4*>(Zs + row * SROW + seg * 8) = u;
        }

        // prefetch next tile (latency hidden under MMA)
        const int nt = tile + gridDim.x;
        if (nt < ntiles) {
#pragma unroll
            for (int i = 0; i < 4; ++i) {
                const int idx = tid + i * 256;
                const int row = idx >> 5, seg = idx & 31;
                const int gr = nt * BM + row;
                if (gr < batch) {
                    const float4* p =
                        reinterpret_cast<const float4*>(Z + (size_t)gr * NVARS + seg * 8);
                    pf[2 * i] = p[0];
                    pf[2 * i + 1] = p[1];
                } else {
                    pf[2 * i] = make_float4(0, 0, 0, 0);
                    pf[2 * i + 1] = make_float4(0, 0, 0, 0);
                }
            }
        }

        __syncthreads();

        // --- mainloop ---
        const uint32_t zbase = smem_to_u32(Zs);
        const uint32_t aaddr = zbase + (uint32_t)arow * (SROW * 2) + acb;

        float acc[8][4];
#pragma unroll
        for (int nj = 0; nj < 8; ++nj)
#pragma unroll
            for (int e = 0; e < 4; ++e) acc[nj][e] = 0.0f;

#pragma unroll
        for (int k = 0; k < 16; ++k) {
            uint32_t a[4], b[4][4];
            ldmx4(a, aaddr + k * 32);
#pragma unroll
            for (int bj = 0; bj < 4; ++bj) ldmx4(b[bj], baddr[bj] + k * 32);
#pragma unroll
            for (int nj = 0; nj < 8; ++nj) {
                const int bj = nj >> 1;
                const int hi = (nj & 1) * 2;
                mma16816(acc[nj], a, b[bj][hi + 0], b[bj][hi + 1]);
            }
        }

        // --- epilogue: out = Z(fp32, L2-hot) + acc ---
        const int r0 = tile * BM + wm * 16 + rrow;
        const int r1 = r0 + 8;
#pragma unroll
        for (int nj = 0; nj < 8; ++nj) {
            const int c = wn * 64 + nj * 8 + rcol;
            if (r0 < batch) {
                const float2 z0 = *reinterpret_cast<const float2*>(Z + (size_t)r0 * NVARS + c);
                float2 o0;
                o0.x = z0.x + acc[nj][0];
                o0.y = z0.y + acc[nj][1];
                *reinterpret_cast<float2*>(out + (size_t)r0 * NVARS + c) = o0;
            }
            if (r1 < batch) {
                const float2 z1 = *reinterpret_cast<const float2*>(Z + (size_t)r1 * NVARS + c);
                float2 o1;
                o1.x = z1.x + acc[nj][2];
                o1.y = z1.y + acc[nj][3];
                *reinterpret_cast<float2*>(out + (size_t)r1 * NVARS + c) = o1;
            }
        }

        parity ^= 1;
    }
}

// ---------------------------------------------------------------------------
extern "C" void kernel_launch(void* const* d_in, const int* in_sizes, int n_in,
                              void* d_out, int out_size) {
    const float* Z = (const float*)d_in[0];
    const float* A = (const float*)d_in[1];
    float* out = (float*)d_out;
    const int batch = in_sizes[0] / NVARS;
    const int ntiles = (batch + BM - 1) / BM;

    cudaFuncSetAttribute(gemm_kernel, cudaFuncAttributeMaxDynamicSharedMemorySize,
                         SMEM_BYTES);

    transpose_kernel<<<dim3(8, 8), dim3(32, 8)>>>(A);
    blockinv_kernel<<<1, 256>>>(A);
    invmain_kernel<<<32, 256>>>();

    int grid = 152;
    if (ntiles < grid) grid = ntiles;
    gemm_kernel<<<grid, 256, SMEM_BYTES>>>(Z, out, batch, ntiles);
}